// round 2
// baseline (speedup 1.0000x reference)
#include <cuda_runtime.h>
#include <float.h>

// Fused MaxPool(2x2,s1,SAME-after) -> depthwise 3x3 binomial blur (zero pad)
// -> AvgPool(2x2,s2). Collapsed to a separable 4x4 stencil w=(1,3,3,1)/8,
// stride 2, over the maxpool output y (computed on the fly via column
// pair-maxes).
//
// R2: warp-strip version. One warp = 2 output rows x 14 output cols, sliding
// across x columns with a 2-slot accumulator ring. Small register footprint
// -> high occupancy -> enough MLP to saturate HBM.

#define WCHUNK 14                // output cols per strip
#define NCH    4                 // 56 / WCHUNK
#define NROWP  28                // 56 / 2 output row-pairs
#define NXROWS 7                 // x rows per strip
#define NY     6                 // y rows per strip
#define NSTEP  (2*WCHUNK + 2)    // 30 sliding steps (ty = 0..29)

__device__ __forceinline__ float4 f4max(float4 a, float4 b) {
    return make_float4(fmaxf(a.x,b.x), fmaxf(a.y,b.y),
                       fmaxf(a.z,b.z), fmaxf(a.w,b.w));
}
__device__ __forceinline__ void f4fma(float4& acc, float w, float4 v) {
    acc.x = fmaf(w, v.x, acc.x);
    acc.y = fmaf(w, v.y, acc.y);
    acc.z = fmaf(w, v.z, acc.z);
    acc.w = fmaf(w, v.w, acc.w);
}

__global__ void __launch_bounds__(64, 8)
mbp_kernel(const float4* __restrict__ x, float4* __restrict__ out) {
    const int lane  = threadIdx.x;                    // channel vec 0..31
    const int strip = blockIdx.x * 2 + threadIdx.y;   // 3584 strips

    const int cj = strip % NCH;
    const int s2 = strip / NCH;
    const int ti = s2 % NROWP;
    const int b  = s2 / NROWP;

    const int oi0 = ti * 2;
    const int oj0 = cj * WCHUNK;
    const int xr0 = 4*ti - 1;          // first x row
    const int xc0 = 2*oj0 - 1;         // first x col (prime column)

    const float4 NEG  = make_float4(-FLT_MAX,-FLT_MAX,-FLT_MAX,-FLT_MAX);
    const float4 ZERO = make_float4(0.f,0.f,0.f,0.f);
    const float wv0 = 0.125f, wv1 = 0.375f;          // (1,3,3,1)/8

    const float4* xb = x + ((size_t)b * 112 * 112) * 32 + lane;

    bool rowOk[NXROWS];
    const float4* rowPtr[NXROWS];
#pragma unroll
    for (int k = 0; k < NXROWS; k++) {
        int gr = xr0 + k;
        rowOk[k] = (gr >= 0) && (gr < 112);
        rowPtr[k] = xb + (long long)gr * 112 * 32;   // only deref if rowOk
    }

    const bool topZero   = (ti == 0);          // y row -1  -> blur zero
    const bool botZero   = (ti == NROWP - 1);  // y row 112 -> blur zero
    const bool leftSkip  = (cj == 0);          // y col -1 at ty=0
    const bool rightSkip = (cj == NCH - 1);    // y col 112 at ty=29

    // Prime: column pair-maxes at x col xc0
    float4 cmPrev[NY];
    {
        const int gc = xc0;
        const bool colOk = (gc >= 0);
        float4 xv[NXROWS];
#pragma unroll
        for (int k = 0; k < NXROWS; k++)
            xv[k] = (colOk && rowOk[k]) ? __ldg(rowPtr[k] + (size_t)gc * 32) : NEG;
#pragma unroll
        for (int k = 0; k < NY; k++) cmPrev[k] = f4max(xv[k], xv[k+1]);
    }

    // Accumulator ring: [row][slot], slot = out-col & 1
    float4 accS[2][2];
    accS[0][0]=ZERO; accS[0][1]=ZERO; accS[1][0]=ZERO; accS[1][1]=ZERO;

    float4* ob = out + (((size_t)b * 56 + oi0) * 56 + oj0) * 32 + lane;

#pragma unroll
    for (int ty = 0; ty < NSTEP; ty++) {
        const int gc = xc0 + ty + 1;               // >= 1
        const bool colOk = (gc < 112);
        float4 xv[NXROWS];
#pragma unroll
        for (int k = 0; k < NXROWS; k++)
            xv[k] = (colOk && rowOk[k]) ? __ldg(rowPtr[k] + (size_t)gc * 32) : NEG;

        float4 cm[NY];
#pragma unroll
        for (int k = 0; k < NY; k++) cm[k] = f4max(xv[k], xv[k+1]);

        // y column finalized this step: global j = 2*oj0 - 1 + ty
        const bool ySkip = (ty == 0 && leftSkip) || (ty == NSTEP-1 && rightSkip);
        if (!ySkip) {
            float4 yc[NY];
#pragma unroll
            for (int k = 0; k < NY; k++) yc[k] = f4max(cmPrev[k], cm[k]);
            if (topZero) yc[0]    = ZERO;
            if (botZero) yc[NY-1] = ZERO;

            const int m  = ty >> 1;          // compile-time after unroll
            const int dj = ty & 1;
            const float wA = dj ? wv1 : wv0;
            const float wB = dj ? wv0 : wv1;
            const int slotA = m & 1;
            const int slotB = slotA ^ 1;
#pragma unroll
            for (int rl = 0; rl < 2; rl++) {
                float4 V = ZERO;
                f4fma(V, wv0, yc[2*rl + 0]);
                f4fma(V, wv1, yc[2*rl + 1]);
                f4fma(V, wv1, yc[2*rl + 2]);
                f4fma(V, wv0, yc[2*rl + 3]);
                if (m < WCHUNK) f4fma(accS[rl][slotA], wA, V);
                if (m >= 1)     f4fma(accS[rl][slotB], wB, V);
            }
        }

        // Col wl = (ty>>1) - 1 completes at odd ty >= 3
        if ((ty & 1) && ty >= 3) {
            const int wl   = (ty >> 1) - 1;
            const int slot = wl & 1;
#pragma unroll
            for (int rl = 0; rl < 2; rl++) {
                ob[((size_t)rl * 56 + wl) * 32] = accS[rl][slot];
                accS[rl][slot] = ZERO;
            }
        }

#pragma unroll
        for (int k = 0; k < NY; k++) cmPrev[k] = cm[k];
    }
}

extern "C" void kernel_launch(void* const* d_in, const int* in_sizes, int n_in,
                              void* d_out, int out_size) {
    const float4* x = (const float4*)d_in[0];   // (32,112,112,128) f32
    // d_in[1] = blur kernel, baked into (1,3,3,1)/8
    float4* out = (float4*)d_out;               // (32,56,56,128) f32

    const int strips = 32 * NROWP * NCH;        // 3584
    dim3 block(32, 2);                          // 2 warps per CTA
    dim3 grid(strips / 2);                      // 1792 blocks
    mbp_kernel<<<grid, block>>>(x, out);
}

// round 3
// speedup vs baseline: 1.5162x; 1.5162x over previous
#include <cuda_runtime.h>
#include <float.h>

// Fused MaxPool(2x2,s1,SAME) -> depthwise 3x3 binomial blur -> AvgPool(2x2,s2)
// == separable 4x4 stencil w=(1,3,3,1)/8, stride 2, over maxpool output y.
// R3: float2 lanes (warp = 64 channels), explicit 2-column double-buffered
// prefetch so each warp always has 14 loads in flight while computing.

#define NROWP  28
#define ROWSTR (112*64)     // float2 per x row
#define PXSTR  64           // float2 per pixel

__device__ __forceinline__ float2 f2max(float2 a, float2 b) {
    return make_float2(fmaxf(a.x,b.x), fmaxf(a.y,b.y));
}
__device__ __forceinline__ void f2fma(float2& a, float w, float2 v) {
    a.x = fmaf(w, v.x, a.x); a.y = fmaf(w, v.y, a.y);
}

// Load 7 x-rows of one column. Rows 1..4 are always in range; row 0 only
// invalid for the top strip, rows 5,6 only for the bottom strip.
#define LOADCOL(dst, c, cOk) do {                                         \
    const float2* _p = base + (long long)(c) * PXSTR;                     \
    dst[0] = ((cOk) && okTop) ? __ldg(_p)              : NEG;             \
    dst[1] = (cOk) ? __ldg(_p + 1*ROWSTR) : NEG;                          \
    dst[2] = (cOk) ? __ldg(_p + 2*ROWSTR) : NEG;                          \
    dst[3] = (cOk) ? __ldg(_p + 3*ROWSTR) : NEG;                          \
    dst[4] = (cOk) ? __ldg(_p + 4*ROWSTR) : NEG;                          \
    dst[5] = ((cOk) && okBot) ? __ldg(_p + 5*ROWSTR) : NEG;               \
    dst[6] = ((cOk) && okBot) ? __ldg(_p + 6*ROWSTR) : NEG;               \
} while (0)

// Finalize one y column (TY is a literal after unroll): vertical (1,3,3,1)/8
// reduction then scatter into the two pending output-column accumulators.
#define STEP(prevcm, curcm, TY) do {                                      \
    const bool _skip = ((TY)==0 && leftSkip) || ((TY)==29 && rightSkip);  \
    if (!_skip) {                                                         \
        float2 yc[6];                                                     \
        _Pragma("unroll")                                                 \
        for (int _k = 0; _k < 6; _k++) yc[_k] = f2max(prevcm[_k], curcm[_k]); \
        if (!okTop) yc[0] = ZERO;                                         \
        if (!okBot) yc[5] = ZERO;                                         \
        const int   _m  = (TY) >> 1;                                      \
        const float _wA = ((TY) & 1) ? wv1 : wv0;                         \
        const float _wB = ((TY) & 1) ? wv0 : wv1;                         \
        _Pragma("unroll")                                                 \
        for (int _rl = 0; _rl < 2; _rl++) {                               \
            float2 V = ZERO;                                              \
            f2fma(V, wv0, yc[2*_rl + 0]);                                 \
            f2fma(V, wv1, yc[2*_rl + 1]);                                 \
            f2fma(V, wv1, yc[2*_rl + 2]);                                 \
            f2fma(V, wv0, yc[2*_rl + 3]);                                 \
            if (_m < 14) f2fma(acc[_rl][_m & 1], _wA, V);                 \
            if (_m >= 1) f2fma(acc[_rl][(_m & 1) ^ 1], _wB, V);           \
        }                                                                 \
    }                                                                     \
} while (0)

__global__ void __launch_bounds__(128, 4)
mbp_kernel(const float2* __restrict__ x, float2* __restrict__ out) {
    const int lane   = threadIdx.x;
    const int wid    = blockIdx.x * 4 + threadIdx.y;   // 7168 warp tasks
    const int chHalf = wid & 1;
    const int strip  = wid >> 1;                       // 3584 strips
    const int cj = strip & 3;                          // 4 col chunks of 14
    const int s2 = strip >> 2;
    const int ti = s2 % NROWP;                         // 28 row pairs
    const int b  = s2 / NROWP;

    const int oi0 = 2 * ti;
    const int oj0 = 14 * cj;
    const int xr0 = 4 * ti - 1;
    const int xc0 = 28 * cj - 1;

    const float2 NEG  = make_float2(-FLT_MAX, -FLT_MAX);
    const float2 ZERO = make_float2(0.f, 0.f);
    const float wv0 = 0.125f, wv1 = 0.375f;            // (1,3,3,1)/8

    const bool okTop     = (ti != 0);
    const bool okBot     = (ti != NROWP - 1);
    const bool leftSkip  = (cj == 0);
    const bool rightSkip = (cj == 3);

    const float2* base = x + (size_t)b * 112 * 112 * 64 + chHalf * 32 + lane
                           + (long long)xr0 * ROWSTR;

    // Prime column xc0 -> cmPrev (column pair-maxes over x rows k,k+1)
    float2 cmPrev[6];
    {
        float2 xv[7];
        LOADCOL(xv, xc0, !leftSkip);                   // xc0 < 0 only if cj==0
#pragma unroll
        for (int k = 0; k < 6; k++) cmPrev[k] = f2max(xv[k], xv[k+1]);
    }

    float2 acc[2][2];                                  // [row][col&1] ring
    acc[0][0]=ZERO; acc[0][1]=ZERO; acc[1][0]=ZERO; acc[1][1]=ZERO;

    float2* ob = out + ((size_t)(b * 56 + oi0) * 56 + oj0) * 64
                     + chHalf * 32 + lane;

    // Double-buffered column pairs: buffer i&1 holds cols of iteration i.
    float2 xa[2][7], xb2[2][7];
    LOADCOL(xa[0],  xc0 + 1, true);
    LOADCOL(xb2[0], xc0 + 2, true);

#pragma unroll
    for (int i = 0; i < 15; i++) {
        const int cur = i & 1, nxt = cur ^ 1;
        if (i < 14) {                                  // prefetch iter i+1
            const bool ok = (i < 13) || !rightSkip;    // only cols 112/113 bad
            LOADCOL(xa[nxt],  xc0 + 3 + 2*i, ok);
            LOADCOL(xb2[nxt], xc0 + 4 + 2*i, ok);
        }

        float2 cmA[6], cmB[6];
#pragma unroll
        for (int k = 0; k < 6; k++) {
            cmA[k] = f2max(xa[cur][k],  xa[cur][k+1]);
            cmB[k] = f2max(xb2[cur][k], xb2[cur][k+1]);
        }

        STEP(cmPrev, cmA, 2*i);                        // y col ty = 2i
        STEP(cmA,    cmB, 2*i + 1);                    // y col ty = 2i+1

        if (i >= 1) {                                  // out col i-1 done
            const int wl = i - 1, slot = wl & 1;
#pragma unroll
            for (int rl = 0; rl < 2; rl++) {
                ob[((size_t)rl * 56 + wl) * 64] = acc[rl][slot];
                acc[rl][slot] = ZERO;
            }
        }

#pragma unroll
        for (int k = 0; k < 6; k++) cmPrev[k] = cmB[k];
    }
}

extern "C" void kernel_launch(void* const* d_in, const int* in_sizes, int n_in,
                              void* d_out, int out_size) {
    const float2* x = (const float2*)d_in[0];   // (32,112,112,128) f32
    // d_in[1] = blur kernel, baked into (1,3,3,1)/8
    float2* out = (float2*)d_out;               // (32,56,56,128) f32

    // 3584 strips x 2 channel halves = 7168 warp tasks, 4 warps/block
    dim3 block(32, 4);
    dim3 grid(7168 / 4);                        // 1792 blocks
    mbp_kernel<<<grid, block>>>(x, out);
}